// round 14
// baseline (speedup 1.0000x reference)
#include <cuda_runtime.h>
#include <math.h>
#include <float.h>

// Problem constants (fixed by setup_inputs)
#define BB 4
#define CC 256
#define MM 1024
#define NN 16384
#define HH 224
#define WW 224
#define HWH (HH*WW)
#define KPOOL 4
#define OH (HH/KPOOL)   // 56
#define OW (WW/KPOOL)   // 56
#define PP (OH*OW)      // 3136 pool cells
#define TPB 128         // threads per block in fused kernel
#define NP  32          // points per block (4 threads/point)
#define QS  (MM/4)      // 256 centers per thread-scan

// Scratch (zero-initialized at module load; every launch restores zeros)
__device__ float g_xt[(size_t)BB * MM * CC];    // fp32 transposed feats [b][m][c] (4MB)
__device__ float g_pool[(size_t)BB * PP * CC];  // pooled accumulator (12.8MB)
__device__ float g_cnt[(size_t)BB * HWH];       // per-pixel point count (800KB)

// ---------------------------------------------------------------------------
// Bit-exact helpers (DO NOT TOUCH — these fix the discrete selection/binning)
// ---------------------------------------------------------------------------
__device__ __forceinline__ float norm3_ref(float x, float y, float z) {
    return __fadd_rn(__fadd_rn(__fmul_rn(x, x), __fmul_rn(y, y)), __fmul_rn(z, z));
}
// Projection row: NO-FMA ascending chain (matches XLA elementwise lowering)
__device__ __forceinline__ float proj_row(float k0, float k1, float k2,
                                          float x, float y, float z) {
    return __fadd_rn(__fadd_rn(__fmul_rn(k0, x), __fmul_rn(k1, y)), __fmul_rn(k2, z));
}
__device__ __forceinline__ int pixel_of(const float* __restrict__ Km,
                                        float px, float py, float pz) {
    float uz0 = proj_row(Km[0], Km[1], Km[2], px, py, pz);
    float uz1 = proj_row(Km[3], Km[4], Km[5], px, py, pz);
    float uz2 = proj_row(Km[6], Km[7], Km[8], px, py, pz);
    float zden = fmaxf(uz2, 1e-8f);
    float uf = floorf(__fdiv_rn(uz0, zden));
    float vf = floorf(__fdiv_rn(uz1, zden));
    int u = (int)fminf(fmaxf(uf, 0.0f), (float)(WW - 1));
    int v = (int)fminf(fmaxf(vf, 0.0f), (float)(HH - 1));
    return v * WW + u;
}
__device__ __forceinline__ float dist_exact(float px, float py, float pz, float pn,
                                            float4 c) {
    float dot = fmaf(pz, c.z, fmaf(py, c.y, __fmul_rn(px, c.x)));
    return __fsub_rn(__fadd_rn(pn, c.w), __fmul_rn(2.0f, dot));
}
// strict-< insert, first-processed-wins-ties (ascending processing order)
__device__ __forceinline__ void ins3(float d, int m,
                                     float& d0, float& d1, float& d2,
                                     int& i0, int& i1, int& i2) {
    if (d < d2) {
        if (d < d1) {
            d2 = d1; i2 = i1;
            if (d < d0) { d1 = d0; i1 = i0; d0 = d; i0 = m; }
            else        { d1 = d;  i1 = m; }
        } else { d2 = d; i2 = m; }
    }
}
__device__ __forceinline__ void red_add_v4(float* addr, float4 v) {
    asm volatile("red.global.add.v4.f32 [%0], {%1, %2, %3, %4};"
                 :: "l"(addr), "f"(v.x), "f"(v.y), "f"(v.z), "f"(v.w)
                 : "memory");
}

// ---------------------------------------------------------------------------
// Kernel 1: transpose xyz_feats [B][C][M] -> g_xt [B][M][C]
// ---------------------------------------------------------------------------
__global__ void k_transpose(const float* __restrict__ X) {
    __shared__ float tile[32][33];
    int b  = blockIdx.z;
    int m0 = blockIdx.x * 32;
    int c0 = blockIdx.y * 32;
    int tx = threadIdx.x, ty = threadIdx.y;  // block (32,8)
    #pragma unroll
    for (int k = 0; k < 32; k += 8)
        tile[ty + k][tx] = X[((size_t)b * CC + (c0 + ty + k)) * MM + (m0 + tx)];
    __syncthreads();
    #pragma unroll
    for (int k = 0; k < 32; k += 8)
        g_xt[((size_t)b * MM + (m0 + ty + k)) * CC + (c0 + tx)] = tile[tx][ty + k];
}

// ---------------------------------------------------------------------------
// Kernel 2: per-pixel point counts (tiny)
// ---------------------------------------------------------------------------
__global__ void __launch_bounds__(256) k_count(
    const float* __restrict__ pts, const float* __restrict__ Km)
{
    int b = blockIdx.y;
    int n = blockIdx.x * 256 + threadIdx.x;
    const float* p = &pts[((size_t)b * NN + n) * 3];
    int pix = pixel_of(Km, p[0], p[1], p[2]);
    atomicAdd(&g_cnt[(size_t)b * HWH + pix], 1.0f);
}

// ---------------------------------------------------------------------------
// Kernel 3: fused 3-NN (4 threads/point, shfl merge) + warp scatter.
// grid (NN/NP=512, BB), 128 threads. 8192 warps total -> latency hidden.
// ---------------------------------------------------------------------------
__global__ void __launch_bounds__(TPB) k_knn_scatter(
    const float* __restrict__ pts,   // [B][N][3]
    const float* __restrict__ ctr,   // [B][M][3]
    const float* __restrict__ Km)    // [3][3]
{
    __shared__ float4 sc[MM];        // centers (x,y,z,|c|^2)  16KB
    __shared__ int4   stg_i[NP];     // (i0,i1,i2,dstCellBase)
    __shared__ float4 stg_w[NP];     // (w0s,w1s,w2s,-)

    int b    = blockIdx.y;
    int tid  = threadIdx.x;
    int lane = tid & 31;
    int h    = tid & 3;              // quarter id
    int pi   = tid >> 2;             // point within block (0..31)

    for (int i = tid; i < MM; i += TPB) {
        float x = ctr[((size_t)b * MM + i) * 3 + 0];
        float y = ctr[((size_t)b * MM + i) * 3 + 1];
        float z = ctr[((size_t)b * MM + i) * 3 + 2];
        sc[i] = make_float4(x, y, z, norm3_ref(x, y, z));
    }
    __syncthreads();

    int n = blockIdx.x * NP + pi;    // grid.x = NN/NP -> exact
    const float* p = &pts[((size_t)b * NN + n) * 3];
    float px = p[0], py = p[1], pz = p[2];
    float pn = norm3_ref(px, py, pz);

    // ---- scan this thread's quarter: strict-<, ascending m ----
    float d0 = FLT_MAX, d1 = FLT_MAX, d2 = FLT_MAX;
    int   i0 = 0, i1 = 0, i2 = 0;
    int mbase = h * QS;
    #pragma unroll 4
    for (int m = 0; m < QS; m++) {
        float d = dist_exact(px, py, pz, pn, sc[mbase + m]);
        ins3(d, mbase + m, d0, d1, d2, i0, i1, i2);
    }

    // ---- merge across the 4 threads of this point (xor 1, then xor 2).
    // Receiver inserts partner's ascending triple AFTER its own state; the
    // kept result (h==0 path) always merges lower-index ranges first, so
    // tie-breaks match a single ascending scan of all 1024 centers.
    #pragma unroll
    for (int step = 1; step <= 2; step <<= 1) {
        float od0 = __shfl_xor_sync(0xFFFFFFFF, d0, step);
        float od1 = __shfl_xor_sync(0xFFFFFFFF, d1, step);
        float od2 = __shfl_xor_sync(0xFFFFFFFF, d2, step);
        int   oi0 = __shfl_xor_sync(0xFFFFFFFF, i0, step);
        int   oi1 = __shfl_xor_sync(0xFFFFFFFF, i1, step);
        int   oi2 = __shfl_xor_sync(0xFFFFFFFF, i2, step);
        ins3(od0, oi0, d0, d1, d2, i0, i1, i2);
        ins3(od1, oi1, d0, d1, d2, i0, i1, i2);
        ins3(od2, oi2, d0, d1, d2, i0, i1, i2);
    }

    if (h == 0) {
        // ---- weights (exact IEEE divisions) ----
        float w0 = __fdiv_rn(1.0f, __fadd_rn(d0, 1e-8f));
        float w1 = __fdiv_rn(1.0f, __fadd_rn(d1, 1e-8f));
        float w2 = __fdiv_rn(1.0f, __fadd_rn(d2, 1e-8f));
        float ws = __fadd_rn(__fadd_rn(w0, w1), w2);
        w0 = __fdiv_rn(w0, ws); w1 = __fdiv_rn(w1, ws); w2 = __fdiv_rn(w2, ws);

        // ---- pixel + per-point scale = (1/count) * (1/16) ----
        int pix = pixel_of(Km, px, py, pz);
        float cnt = g_cnt[(size_t)b * HWH + pix];
        float scale = __fdiv_rn(1.0f, cnt) * 0.0625f;
        int v = pix / WW, u = pix % WW;
        int cell = (v >> 2) * OW + (u >> 2);
        int dstBase = (b * PP + cell) * CC;

        stg_i[pi] = make_int4(i0, i1, i2, dstBase);
        stg_w[pi] = make_float4(w0 * scale, w1 * scale, w2 * scale, 0.0f);
    }
    __syncwarp();   // warp w's 8 points are staged by warp w itself

    // ---- warp-cooperative gather + vector scatter (8 points per warp) ----
    const float4* xt4 = reinterpret_cast<const float4*>(g_xt);
    int pw = (tid >> 5) * 8;         // this warp's first point
    #pragma unroll 2
    for (int k = 0; k < 8; k++) {
        int4   si = stg_i[pw + k];   // broadcast
        float4 sw = stg_w[pw + k];
        const float4* r0 = xt4 + ((size_t)b * MM + si.x) * (CC / 4);
        const float4* r1 = xt4 + ((size_t)b * MM + si.y) * (CC / 4);
        const float4* r2 = xt4 + ((size_t)b * MM + si.z) * (CC / 4);
        float* dp = &g_pool[si.w];
        #pragma unroll
        for (int j = 0; j < 2; j++) {
            int c4 = j * 32 + lane;
            float4 a  = __ldg(&r0[c4]);
            float4 bq = __ldg(&r1[c4]);
            float4 cq = __ldg(&r2[c4]);
            float4 f;
            f.x = fmaf(sw.x, a.x, fmaf(sw.y, bq.x, sw.z * cq.x));
            f.y = fmaf(sw.x, a.y, fmaf(sw.y, bq.y, sw.z * cq.y));
            f.z = fmaf(sw.x, a.z, fmaf(sw.y, bq.z, sw.z * cq.z));
            f.w = fmaf(sw.x, a.w, fmaf(sw.y, bq.w, sw.z * cq.w));
            red_add_v4(dp + c4 * 4, f);
        }
    }
}

// ---------------------------------------------------------------------------
// Kernel 4: vectorized transpose g_pool [b][p][c] -> out [b][c][p] + clear.
// Tile: 64 cells x 64 channels. grid (49, 4, 4); block 256.
// ---------------------------------------------------------------------------
__global__ void __launch_bounds__(256) k_pool_out(float* __restrict__ out) {
    __shared__ float tile[64][65];
    int b  = blockIdx.z;
    int c0 = blockIdx.y * 64;
    int p0 = blockIdx.x * 64;
    int tid = threadIdx.x;

    float4 v[4];
    #pragma unroll
    for (int r = 0; r < 4; r++) {
        int w = tid + 256 * r;
        int cell = w >> 4, c4 = w & 15;
        size_t idx = ((size_t)b * PP + p0 + cell) * CC + c0 + c4 * 4;
        v[r] = *reinterpret_cast<const float4*>(&g_pool[idx]);
    }
    const float4 z4 = make_float4(0.f, 0.f, 0.f, 0.f);
    #pragma unroll
    for (int r = 0; r < 4; r++) {
        int w = tid + 256 * r;
        int cell = w >> 4, c4 = w & 15;
        size_t idx = ((size_t)b * PP + p0 + cell) * CC + c0 + c4 * 4;
        *reinterpret_cast<float4*>(&g_pool[idx]) = z4;   // restore invariant
        tile[cell][c4 * 4 + 0] = v[r].x;
        tile[cell][c4 * 4 + 1] = v[r].y;
        tile[cell][c4 * 4 + 2] = v[r].z;
        tile[cell][c4 * 4 + 3] = v[r].w;
    }
    if (blockIdx.y == 0) {
        #pragma unroll
        for (int k = 0; k < 4; k++) {
            int i = blockIdx.x * 256 + tid + k * (49 * 256);
            g_cnt[(size_t)b * HWH + i] = 0.0f;   // 49*256*4 = 50176 = HWH
        }
    }
    __syncthreads();

    #pragma unroll
    for (int r = 0; r < 4; r++) {
        int w = tid + 256 * r;
        int c = w >> 4, p4 = w & 15;
        float4 f;
        f.x = tile[p4 * 4 + 0][c];
        f.y = tile[p4 * 4 + 1][c];
        f.z = tile[p4 * 4 + 2][c];
        f.w = tile[p4 * 4 + 3][c];
        *reinterpret_cast<float4*>(&out[((size_t)b * CC + c0 + c) * PP + p0 + p4 * 4]) = f;
    }
}

// ---------------------------------------------------------------------------
extern "C" void kernel_launch(void* const* d_in, const int* in_sizes, int n_in,
                              void* d_out, int out_size) {
    const float* feats = (const float*)d_in[0];  // [B][C][M]
    const float* pts   = (const float*)d_in[1];  // [B][N][3]
    const float* ctr   = (const float*)d_in[2];  // [B][M][3]
    const float* Km    = (const float*)d_in[3];  // [3][3]
    float* out = (float*)d_out;

    k_transpose<<<dim3(MM / 32, CC / 32, BB), dim3(32, 8)>>>(feats);
    k_count<<<dim3(NN / 256, BB), 256>>>(pts, Km);
    k_knn_scatter<<<dim3(NN / NP, BB), TPB>>>(pts, ctr, Km);
    k_pool_out<<<dim3(PP / 64, CC / 64, BB), 256>>>(out);
}

// round 15
// speedup vs baseline: 1.3447x; 1.3447x over previous
#include <cuda_runtime.h>
#include <math.h>
#include <float.h>
#include <limits.h>

// Problem constants (fixed by setup_inputs)
#define BB 4
#define CC 256
#define MM 1024
#define NN 16384
#define HH 224
#define WW 224
#define HWH (HH*WW)
#define KPOOL 4
#define OH (HH/KPOOL)   // 56
#define OW (WW/KPOOL)   // 56
#define PP (OH*OW)      // 3136 pool cells
#define TPB 128         // threads per block in fused kernel
#define NP  32          // points per block (4 threads/point)
#define QS  (MM/4)      // 256 centers per thread-scan (stride-4 interleaved)

// Scratch (zero-initialized at module load; every launch restores zeros)
__device__ float g_xt[(size_t)BB * MM * CC];    // fp32 transposed feats [b][m][c] (4MB)
__device__ float g_pool[(size_t)BB * PP * CC];  // pooled accumulator (12.8MB)
__device__ float g_cnt[(size_t)BB * HWH];       // per-pixel point count (800KB)

// ---------------------------------------------------------------------------
// Bit-exact helpers (DO NOT TOUCH — these fix the discrete selection/binning)
// ---------------------------------------------------------------------------
__device__ __forceinline__ float norm3_ref(float x, float y, float z) {
    return __fadd_rn(__fadd_rn(__fmul_rn(x, x), __fmul_rn(y, y)), __fmul_rn(z, z));
}
// Projection row: NO-FMA ascending chain (matches XLA elementwise lowering)
__device__ __forceinline__ float proj_row(float k0, float k1, float k2,
                                          float x, float y, float z) {
    return __fadd_rn(__fadd_rn(__fmul_rn(k0, x), __fmul_rn(k1, y)), __fmul_rn(k2, z));
}
__device__ __forceinline__ int pixel_of(const float* __restrict__ Km,
                                        float px, float py, float pz) {
    float uz0 = proj_row(Km[0], Km[1], Km[2], px, py, pz);
    float uz1 = proj_row(Km[3], Km[4], Km[5], px, py, pz);
    float uz2 = proj_row(Km[6], Km[7], Km[8], px, py, pz);
    float zden = fmaxf(uz2, 1e-8f);
    float uf = floorf(__fdiv_rn(uz0, zden));
    float vf = floorf(__fdiv_rn(uz1, zden));
    int u = (int)fminf(fmaxf(uf, 0.0f), (float)(WW - 1));
    int v = (int)fminf(fmaxf(vf, 0.0f), (float)(HH - 1));
    return v * WW + u;
}
__device__ __forceinline__ float dist_exact(float px, float py, float pz, float pn,
                                            float4 c) {
    float dot = fmaf(pz, c.z, fmaf(py, c.y, __fmul_rn(px, c.x)));
    return __fsub_rn(__fadd_rn(pn, c.w), __fmul_rn(2.0f, dot));
}
// Lexicographic (d, index) top-3 insert: order-independent, provably equals
// jax.lax.top_k (ascending distance, ties -> lower index).
__device__ __forceinline__ void ins3t(float d, int m,
                                      float& d0, float& d1, float& d2,
                                      int& i0, int& i1, int& i2) {
    if (d < d2 || (d == d2 && m < i2)) {
        if (d < d1 || (d == d1 && m < i1)) {
            d2 = d1; i2 = i1;
            if (d < d0 || (d == d0 && m < i0)) { d1 = d0; i1 = i0; d0 = d; i0 = m; }
            else                               { d1 = d;  i1 = m; }
        } else { d2 = d; i2 = m; }
    }
}
__device__ __forceinline__ void red_add_v4(float* addr, float4 v) {
    asm volatile("red.global.add.v4.f32 [%0], {%1, %2, %3, %4};"
                 :: "l"(addr), "f"(v.x), "f"(v.y), "f"(v.z), "f"(v.w)
                 : "memory");
}

// ---------------------------------------------------------------------------
// Kernel 1: transpose xyz_feats [B][C][M] -> g_xt [B][M][C]
// ---------------------------------------------------------------------------
__global__ void k_transpose(const float* __restrict__ X) {
    __shared__ float tile[32][33];
    int b  = blockIdx.z;
    int m0 = blockIdx.x * 32;
    int c0 = blockIdx.y * 32;
    int tx = threadIdx.x, ty = threadIdx.y;  // block (32,8)
    #pragma unroll
    for (int k = 0; k < 32; k += 8)
        tile[ty + k][tx] = X[((size_t)b * CC + (c0 + ty + k)) * MM + (m0 + tx)];
    __syncthreads();
    #pragma unroll
    for (int k = 0; k < 32; k += 8)
        g_xt[((size_t)b * MM + (m0 + ty + k)) * CC + (c0 + tx)] = tile[tx][ty + k];
}

// ---------------------------------------------------------------------------
// Kernel 2: per-pixel point counts (tiny)
// ---------------------------------------------------------------------------
__global__ void __launch_bounds__(256) k_count(
    const float* __restrict__ pts, const float* __restrict__ Km)
{
    int b = blockIdx.y;
    int n = blockIdx.x * 256 + threadIdx.x;
    const float* p = &pts[((size_t)b * NN + n) * 3];
    int pix = pixel_of(Km, p[0], p[1], p[2]);
    atomicAdd(&g_cnt[(size_t)b * HWH + pix], 1.0f);
}

// ---------------------------------------------------------------------------
// Kernel 3: fused 3-NN (4 threads/point, STRIDE-4 interleave -> conflict-free
// LDS broadcast) + shfl merge + warp-cooperative scatter.
// grid (NN/NP=512, BB) = 2048 blocks, 128 thr -> 8192 knn warps, ~55 warps/SM.
// ---------------------------------------------------------------------------
__global__ void __launch_bounds__(TPB) k_knn_scatter(
    const float* __restrict__ pts,   // [B][N][3]
    const float* __restrict__ ctr,   // [B][M][3]
    const float* __restrict__ Km)    // [3][3]
{
    __shared__ float4 sc[MM];        // centers (x,y,z,|c|^2)  16KB
    __shared__ int4   stg_i[NP];     // (i0,i1,i2,dstCellBase)
    __shared__ float4 stg_w[NP];     // (w0s,w1s,w2s,-)

    int b    = blockIdx.y;
    int tid  = threadIdx.x;
    int lane = tid & 31;
    int h    = tid & 3;              // interleave phase: scans m = 4*j + h
    int pi   = tid >> 2;             // point within block (0..31)

    for (int i = tid; i < MM; i += TPB) {
        float x = ctr[((size_t)b * MM + i) * 3 + 0];
        float y = ctr[((size_t)b * MM + i) * 3 + 1];
        float z = ctr[((size_t)b * MM + i) * 3 + 2];
        sc[i] = make_float4(x, y, z, norm3_ref(x, y, z));
    }
    __syncthreads();

    int n = blockIdx.x * NP + pi;    // grid.x = NN/NP -> exact
    const float* p = &pts[((size_t)b * NN + n) * 3];
    float px = p[0], py = p[1], pz = p[2];
    float pn = norm3_ref(px, py, pz);

    // ---- scan interleaved quarter: centers 4*j + h, j = 0..255.
    // At each j the warp touches 4 consecutive float4s (64B) -> conflict-free.
    float d0 = FLT_MAX, d1 = FLT_MAX, d2 = FLT_MAX;
    int   i0 = INT_MAX, i1 = INT_MAX, i2 = INT_MAX;
    #pragma unroll 4
    for (int j = 0; j < QS; j++) {
        int m = 4 * j + h;
        float d = dist_exact(px, py, pz, pn, sc[m]);
        ins3t(d, m, d0, d1, d2, i0, i1, i2);
    }

    // ---- merge across the 4 threads of this point (xor 1, then xor 2).
    // ins3t is order-independent (full (d,idx) tie-break), so the merged
    // result equals top-3 of the union = top_k over all 1024 centers.
    #pragma unroll
    for (int step = 1; step <= 2; step <<= 1) {
        float od0 = __shfl_xor_sync(0xFFFFFFFF, d0, step);
        float od1 = __shfl_xor_sync(0xFFFFFFFF, d1, step);
        float od2 = __shfl_xor_sync(0xFFFFFFFF, d2, step);
        int   oi0 = __shfl_xor_sync(0xFFFFFFFF, i0, step);
        int   oi1 = __shfl_xor_sync(0xFFFFFFFF, i1, step);
        int   oi2 = __shfl_xor_sync(0xFFFFFFFF, i2, step);
        ins3t(od0, oi0, d0, d1, d2, i0, i1, i2);
        ins3t(od1, oi1, d0, d1, d2, i0, i1, i2);
        ins3t(od2, oi2, d0, d1, d2, i0, i1, i2);
    }

    if (h == 0) {
        // ---- weights (exact IEEE divisions) ----
        float w0 = __fdiv_rn(1.0f, __fadd_rn(d0, 1e-8f));
        float w1 = __fdiv_rn(1.0f, __fadd_rn(d1, 1e-8f));
        float w2 = __fdiv_rn(1.0f, __fadd_rn(d2, 1e-8f));
        float ws = __fadd_rn(__fadd_rn(w0, w1), w2);
        w0 = __fdiv_rn(w0, ws); w1 = __fdiv_rn(w1, ws); w2 = __fdiv_rn(w2, ws);

        // ---- pixel + per-point scale = (1/count) * (1/16) ----
        int pix = pixel_of(Km, px, py, pz);
        float cnt = g_cnt[(size_t)b * HWH + pix];
        float scale = __fdiv_rn(1.0f, cnt) * 0.0625f;
        int v = pix / WW, u = pix % WW;
        int cell = (v >> 2) * OW + (u >> 2);
        int dstBase = (b * PP + cell) * CC;

        stg_i[pi] = make_int4(i0, i1, i2, dstBase);
        stg_w[pi] = make_float4(w0 * scale, w1 * scale, w2 * scale, 0.0f);
    }
    __syncwarp();   // warp w's 8 points are staged by warp w itself

    // ---- warp-cooperative gather + vector scatter (8 points per warp) ----
    const float4* xt4 = reinterpret_cast<const float4*>(g_xt);
    int pw = (tid >> 5) * 8;         // this warp's first point
    #pragma unroll 2
    for (int k = 0; k < 8; k++) {
        int4   si = stg_i[pw + k];   // broadcast
        float4 sw = stg_w[pw + k];
        const float4* r0 = xt4 + ((size_t)b * MM + si.x) * (CC / 4);
        const float4* r1 = xt4 + ((size_t)b * MM + si.y) * (CC / 4);
        const float4* r2 = xt4 + ((size_t)b * MM + si.z) * (CC / 4);
        float* dp = &g_pool[si.w];
        #pragma unroll
        for (int j = 0; j < 2; j++) {
            int c4 = j * 32 + lane;
            float4 a  = __ldg(&r0[c4]);
            float4 bq = __ldg(&r1[c4]);
            float4 cq = __ldg(&r2[c4]);
            float4 f;
            f.x = fmaf(sw.x, a.x, fmaf(sw.y, bq.x, sw.z * cq.x));
            f.y = fmaf(sw.x, a.y, fmaf(sw.y, bq.y, sw.z * cq.y));
            f.z = fmaf(sw.x, a.z, fmaf(sw.y, bq.z, sw.z * cq.z));
            f.w = fmaf(sw.x, a.w, fmaf(sw.y, bq.w, sw.z * cq.w));
            red_add_v4(dp + c4 * 4, f);
        }
    }
}

// ---------------------------------------------------------------------------
// Kernel 4: vectorized transpose g_pool [b][p][c] -> out [b][c][p] + clear.
// Tile: 64 cells x 64 channels. grid (49, 4, 4); block 256.
// ---------------------------------------------------------------------------
__global__ void __launch_bounds__(256) k_pool_out(float* __restrict__ out) {
    __shared__ float tile[64][65];
    int b  = blockIdx.z;
    int c0 = blockIdx.y * 64;
    int p0 = blockIdx.x * 64;
    int tid = threadIdx.x;

    float4 v[4];
    #pragma unroll
    for (int r = 0; r < 4; r++) {
        int w = tid + 256 * r;
        int cell = w >> 4, c4 = w & 15;
        size_t idx = ((size_t)b * PP + p0 + cell) * CC + c0 + c4 * 4;
        v[r] = *reinterpret_cast<const float4*>(&g_pool[idx]);
    }
    const float4 z4 = make_float4(0.f, 0.f, 0.f, 0.f);
    #pragma unroll
    for (int r = 0; r < 4; r++) {
        int w = tid + 256 * r;
        int cell = w >> 4, c4 = w & 15;
        size_t idx = ((size_t)b * PP + p0 + cell) * CC + c0 + c4 * 4;
        *reinterpret_cast<float4*>(&g_pool[idx]) = z4;   // restore invariant
        tile[cell][c4 * 4 + 0] = v[r].x;
        tile[cell][c4 * 4 + 1] = v[r].y;
        tile[cell][c4 * 4 + 2] = v[r].z;
        tile[cell][c4 * 4 + 3] = v[r].w;
    }
    if (blockIdx.y == 0) {
        #pragma unroll
        for (int k = 0; k < 4; k++) {
            int i = blockIdx.x * 256 + tid + k * (49 * 256);
            g_cnt[(size_t)b * HWH + i] = 0.0f;   // 49*256*4 = 50176 = HWH
        }
    }
    __syncthreads();

    #pragma unroll
    for (int r = 0; r < 4; r++) {
        int w = tid + 256 * r;
        int c = w >> 4, p4 = w & 15;
        float4 f;
        f.x = tile[p4 * 4 + 0][c];
        f.y = tile[p4 * 4 + 1][c];
        f.z = tile[p4 * 4 + 2][c];
        f.w = tile[p4 * 4 + 3][c];
        *reinterpret_cast<float4*>(&out[((size_t)b * CC + c0 + c) * PP + p0 + p4 * 4]) = f;
    }
}

// ---------------------------------------------------------------------------
extern "C" void kernel_launch(void* const* d_in, const int* in_sizes, int n_in,
                              void* d_out, int out_size) {
    const float* feats = (const float*)d_in[0];  // [B][C][M]
    const float* pts   = (const float*)d_in[1];  // [B][N][3]
    const float* ctr   = (const float*)d_in[2];  // [B][M][3]
    const float* Km    = (const float*)d_in[3];  // [3][3]
    float* out = (float*)d_out;

    k_transpose<<<dim3(MM / 32, CC / 32, BB), dim3(32, 8)>>>(feats);
    k_count<<<dim3(NN / 256, BB), 256>>>(pts, Km);
    k_knn_scatter<<<dim3(NN / NP, BB), TPB>>>(pts, ctr, Km);
    k_pool_out<<<dim3(PP / 64, CC / 64, BB), 256>>>(out);
}

// round 16
// speedup vs baseline: 1.8316x; 1.3621x over previous
#include <cuda_runtime.h>
#include <math.h>
#include <float.h>

// Problem constants (fixed by setup_inputs)
#define BB 4
#define CC 256
#define MM 1024
#define NN 16384
#define HH 224
#define WW 224
#define HWH (HH*WW)
#define KPOOL 4
#define OH (HH/KPOOL)   // 56
#define OW (WW/KPOOL)   // 56
#define PP (OH*OW)      // 3136 pool cells
#define TPB 128         // threads per block in fused kernel

// Scratch (zero-initialized at module load; every launch restores zeros)
__device__ float g_xt[(size_t)BB * MM * CC];    // fp32 transposed feats [b][m][c] (4MB)
__device__ float g_pool[(size_t)BB * PP * CC];  // pooled accumulator (12.8MB)
__device__ float g_cnt[(size_t)BB * HWH];       // per-pixel point count (800KB)

// ---------------------------------------------------------------------------
// Bit-exact helpers (DO NOT TOUCH — these fix the discrete selection/binning)
// ---------------------------------------------------------------------------
__device__ __forceinline__ float norm3_ref(float x, float y, float z) {
    return __fadd_rn(__fadd_rn(__fmul_rn(x, x), __fmul_rn(y, y)), __fmul_rn(z, z));
}
// Projection row: NO-FMA ascending chain (matches XLA elementwise lowering)
__device__ __forceinline__ float proj_row(float k0, float k1, float k2,
                                          float x, float y, float z) {
    return __fadd_rn(__fadd_rn(__fmul_rn(k0, x), __fmul_rn(k1, y)), __fmul_rn(k2, z));
}
__device__ __forceinline__ int pixel_of(const float* __restrict__ Km,
                                        float px, float py, float pz) {
    float uz0 = proj_row(Km[0], Km[1], Km[2], px, py, pz);
    float uz1 = proj_row(Km[3], Km[4], Km[5], px, py, pz);
    float uz2 = proj_row(Km[6], Km[7], Km[8], px, py, pz);
    float zden = fmaxf(uz2, 1e-8f);
    float uf = floorf(__fdiv_rn(uz0, zden));
    float vf = floorf(__fdiv_rn(uz1, zden));
    int u = (int)fminf(fmaxf(uf, 0.0f), (float)(WW - 1));
    int v = (int)fminf(fmaxf(vf, 0.0f), (float)(HH - 1));
    return v * WW + u;
}
__device__ __forceinline__ float dist_exact(float px, float py, float pz, float pn,
                                            float4 c) {
    float dot = fmaf(pz, c.z, fmaf(py, c.y, __fmul_rn(px, c.x)));
    return __fsub_rn(__fadd_rn(pn, c.w), __fmul_rn(2.0f, dot));
}
__device__ __forceinline__ void red_add_v4(float* addr, float4 v) {
    asm volatile("red.global.add.v4.f32 [%0], {%1, %2, %3, %4};"
                 :: "l"(addr), "f"(v.x), "f"(v.y), "f"(v.z), "f"(v.w)
                 : "memory");
}

// ---------------------------------------------------------------------------
// Kernel 1: transpose xyz_feats [B][C][M] -> g_xt [B][M][C]
// ---------------------------------------------------------------------------
__global__ void k_transpose(const float* __restrict__ X) {
    __shared__ float tile[32][33];
    int b  = blockIdx.z;
    int m0 = blockIdx.x * 32;
    int c0 = blockIdx.y * 32;
    int tx = threadIdx.x, ty = threadIdx.y;  // block (32,8)
    #pragma unroll
    for (int k = 0; k < 32; k += 8)
        tile[ty + k][tx] = X[((size_t)b * CC + (c0 + ty + k)) * MM + (m0 + tx)];
    __syncthreads();
    #pragma unroll
    for (int k = 0; k < 32; k += 8)
        g_xt[((size_t)b * MM + (m0 + ty + k)) * CC + (c0 + tx)] = tile[tx][ty + k];
}

// ---------------------------------------------------------------------------
// Kernel 2: per-pixel point counts (tiny)
// ---------------------------------------------------------------------------
__global__ void __launch_bounds__(256) k_count(
    const float* __restrict__ pts, const float* __restrict__ Km)
{
    int b = blockIdx.y;
    int n = blockIdx.x * 256 + threadIdx.x;
    const float* p = &pts[((size_t)b * NN + n) * 3];
    int pix = pixel_of(Km, p[0], p[1], p[2]);
    atomicAdd(&g_cnt[(size_t)b * HWH + pix], 1.0f);
}

// ---------------------------------------------------------------------------
// Kernel 3: fused dense 3-NN + warp-cooperative gather/scatter (R12 shape).
// 128-thr blocks, 512 blocks -> knn(issue) and scatter(latency) phases of
// different blocks overlap on every SM.
// ---------------------------------------------------------------------------
__global__ void __launch_bounds__(TPB) k_knn_scatter(
    const float* __restrict__ pts,   // [B][N][3]
    const float* __restrict__ ctr,   // [B][M][3]
    const float* __restrict__ Km)    // [3][3]
{
    __shared__ float4 sc[MM];        // centers (x,y,z,|c|^2)  16KB
    __shared__ int4   stg_i[TPB];    // (i0,i1,i2,dstCellBase) 2KB
    __shared__ float4 stg_w[TPB];    // (w0s,w1s,w2s,-)        2KB

    int b   = blockIdx.y;
    int tid = threadIdx.x;
    int lane = tid & 31;

    for (int i = tid; i < MM; i += TPB) {
        float x = ctr[((size_t)b * MM + i) * 3 + 0];
        float y = ctr[((size_t)b * MM + i) * 3 + 1];
        float z = ctr[((size_t)b * MM + i) * 3 + 2];
        sc[i] = make_float4(x, y, z, norm3_ref(x, y, z));
    }

    int n = blockIdx.x * TPB + tid;   // grid.x = NN/TPB -> exact
    const float* p = &pts[((size_t)b * NN + n) * 3];
    float px = __ldg(&p[0]), py = __ldg(&p[1]), pz = __ldg(&p[2]);
    float pn = norm3_ref(px, py, pz);

    // ---- pixel + count prefetch: issued BEFORE the 1024-iter loop so the
    // ~600-cycle latency is hidden behind the knn scan.
    int pix = pixel_of(Km, px, py, pz);
    float cnt = __ldg(&g_cnt[(size_t)b * HWH + pix]);

    __syncthreads();

    // ---- dense top-3: strict-<, ascending m (ties -> earliest index) ----
    float d0 = FLT_MAX, d1 = FLT_MAX, d2 = FLT_MAX;
    int   i0 = 0, i1 = 0, i2 = 0;
    #pragma unroll 8
    for (int m = 0; m < MM; m++) {
        float d = dist_exact(px, py, pz, pn, sc[m]);   // broadcast LDS.128
        if (d < d2) {
            if (d < d1) {
                d2 = d1; i2 = i1;
                if (d < d0) { d1 = d0; i1 = i0; d0 = d; i0 = m; }
                else        { d1 = d;  i1 = m; }
            } else { d2 = d; i2 = m; }
        }
    }

    // ---- weights (exact IEEE divisions) ----
    float w0 = __fdiv_rn(1.0f, __fadd_rn(d0, 1e-8f));
    float w1 = __fdiv_rn(1.0f, __fadd_rn(d1, 1e-8f));
    float w2 = __fdiv_rn(1.0f, __fadd_rn(d2, 1e-8f));
    float ws = __fadd_rn(__fadd_rn(w0, w1), w2);
    w0 = __fdiv_rn(w0, ws); w1 = __fdiv_rn(w1, ws); w2 = __fdiv_rn(w2, ws);

    // ---- per-point scale = (1/count) * (1/16); dst cell ----
    float scale = __fdiv_rn(1.0f, cnt) * 0.0625f;
    int v = pix / WW, u = pix % WW;
    int cell = (v >> 2) * OW + (u >> 2);
    int dstBase = (b * PP + cell) * CC;

    stg_i[tid] = make_int4(i0, i1, i2, dstBase);
    stg_w[tid] = make_float4(w0 * scale, w1 * scale, w2 * scale, 0.0f);
    __syncwarp();

    // ---- warp-cooperative gather + vector scatter ----
    const float4* xt4 = reinterpret_cast<const float4*>(g_xt);
    int wbase = tid & ~31;
    #pragma unroll 4
    for (int k = 0; k < 32; k++) {
        int4   si = stg_i[wbase + k];   // broadcast
        float4 sw = stg_w[wbase + k];
        const float4* r0 = xt4 + ((size_t)b * MM + si.x) * (CC / 4);
        const float4* r1 = xt4 + ((size_t)b * MM + si.y) * (CC / 4);
        const float4* r2 = xt4 + ((size_t)b * MM + si.z) * (CC / 4);
        float* dp = &g_pool[si.w];
        #pragma unroll
        for (int j = 0; j < 2; j++) {
            int c4 = j * 32 + lane;
            float4 a  = __ldg(&r0[c4]);
            float4 bq = __ldg(&r1[c4]);
            float4 cq = __ldg(&r2[c4]);
            float4 f;
            f.x = fmaf(sw.x, a.x, fmaf(sw.y, bq.x, sw.z * cq.x));
            f.y = fmaf(sw.x, a.y, fmaf(sw.y, bq.y, sw.z * cq.y));
            f.z = fmaf(sw.x, a.z, fmaf(sw.y, bq.z, sw.z * cq.z));
            f.w = fmaf(sw.x, a.w, fmaf(sw.y, bq.w, sw.z * cq.w));
            red_add_v4(dp + c4 * 4, f);
        }
    }
}

// ---------------------------------------------------------------------------
// Kernel 4: vectorized transpose g_pool [b][p][c] -> out [b][c][p] + clear.
// Tile: 64 cells x 64 channels. grid (49, 4, 4); block 256.
// ---------------------------------------------------------------------------
__global__ void __launch_bounds__(256) k_pool_out(float* __restrict__ out) {
    __shared__ float tile[64][65];
    int b  = blockIdx.z;
    int c0 = blockIdx.y * 64;
    int p0 = blockIdx.x * 64;
    int tid = threadIdx.x;

    float4 v[4];
    #pragma unroll
    for (int r = 0; r < 4; r++) {
        int w = tid + 256 * r;
        int cell = w >> 4, c4 = w & 15;
        size_t idx = ((size_t)b * PP + p0 + cell) * CC + c0 + c4 * 4;
        v[r] = *reinterpret_cast<const float4*>(&g_pool[idx]);
    }
    const float4 z4 = make_float4(0.f, 0.f, 0.f, 0.f);
    #pragma unroll
    for (int r = 0; r < 4; r++) {
        int w = tid + 256 * r;
        int cell = w >> 4, c4 = w & 15;
        size_t idx = ((size_t)b * PP + p0 + cell) * CC + c0 + c4 * 4;
        *reinterpret_cast<float4*>(&g_pool[idx]) = z4;   // restore invariant
        tile[cell][c4 * 4 + 0] = v[r].x;
        tile[cell][c4 * 4 + 1] = v[r].y;
        tile[cell][c4 * 4 + 2] = v[r].z;
        tile[cell][c4 * 4 + 3] = v[r].w;
    }
    if (blockIdx.y == 0) {
        #pragma unroll
        for (int k = 0; k < 4; k++) {
            int i = blockIdx.x * 256 + tid + k * (49 * 256);
            g_cnt[(size_t)b * HWH + i] = 0.0f;   // 49*256*4 = 50176 = HWH
        }
    }
    __syncthreads();

    #pragma unroll
    for (int r = 0; r < 4; r++) {
        int w = tid + 256 * r;
        int c = w >> 4, p4 = w & 15;
        float4 f;
        f.x = tile[p4 * 4 + 0][c];
        f.y = tile[p4 * 4 + 1][c];
        f.z = tile[p4 * 4 + 2][c];
        f.w = tile[p4 * 4 + 3][c];
        *reinterpret_cast<float4*>(&out[((size_t)b * CC + c0 + c) * PP + p0 + p4 * 4]) = f;
    }
}

// ---------------------------------------------------------------------------
extern "C" void kernel_launch(void* const* d_in, const int* in_sizes, int n_in,
                              void* d_out, int out_size) {
    const float* feats = (const float*)d_in[0];  // [B][C][M]
    const float* pts   = (const float*)d_in[1];  // [B][N][3]
    const float* ctr   = (const float*)d_in[2];  // [B][M][3]
    const float* Km    = (const float*)d_in[3];  // [3][3]
    float* out = (float*)d_out;

    k_transpose<<<dim3(MM / 32, CC / 32, BB), dim3(32, 8)>>>(feats);
    k_count<<<dim3(NN / 256, BB), 256>>>(pts, Km);
    k_knn_scatter<<<dim3(NN / TPB, BB), TPB>>>(pts, ctr, Km);
    k_pool_out<<<dim3(PP / 64, CC / 64, BB), 256>>>(out);
}